// round 1
// baseline (speedup 1.0000x reference)
#include <cuda_runtime.h>
#include <stdint.h>

#define B_ 4
#define V_ 778
#define F_ 1538
#define S_ 320
#define TILE 16
#define FPW 193   // ceil(F_/8) faces per warp segment

// Per (batch, face): 3 edges x (A, B, C, pad). d_e = A*px + B*py + C, already
// scaled by sgn * inv_len * log2(e) / sigma  (so t = exp2(-d) = exp(-dist/sigma)).
__device__ float g_coeffs[B_ * F_ * 12];

__global__ void precompute_kernel(const float* __restrict__ verts,
                                  const int* __restrict__ faces) {
    int idx = blockIdx.x * blockDim.x + threadIdx.x;
    if (idx >= B_ * F_) return;
    int b = idx / F_;
    int f = idx - b * F_;
    int i0 = faces[f * 3 + 0], i1 = faces[f * 3 + 1], i2 = faces[f * 3 + 2];
    const float* vb = verts + b * V_ * 3;
    // y is negated: v = verts * [1, -1, 1]
    float x0 = vb[i0 * 3 + 0], y0 = -vb[i0 * 3 + 1];
    float x1 = vb[i1 * 3 + 0], y1 = -vb[i1 * 3 + 1];
    float x2 = vb[i2 * 3 + 0], y2 = -vb[i2 * 3 + 1];
    float area2 = (x1 - x0) * (y2 - y0) - (y1 - y0) * (x2 - x0);
    float sgn = (area2 > 0.f) ? 1.f : ((area2 < 0.f) ? -1.f : 0.f);
    const float INVS = 1.4426950408889634f / 0.01f;  // log2(e) / SIGMA

    float ax[3] = {x0, x1, x2}, ay[3] = {y0, y1, y2};
    float bx[3] = {x1, x2, x0}, by[3] = {y1, y2, y0};
    float* o = g_coeffs + idx * 12;
#pragma unroll
    for (int e = 0; e < 3; e++) {
        float ex = bx[e] - ax[e];
        float ey = by[e] - ay[e];
        float inv_len = 1.0f / (sqrtf(ex * ex + ey * ey) + 1e-8f);
        float k = sgn * inv_len * INVS;
        o[e * 4 + 0] = -k * ey;                      // A (px coeff)
        o[e * 4 + 1] = k * ex;                       // B (py coeff)
        o[e * 4 + 2] = k * (ey * ax[e] - ex * ay[e]); // C
        o[e * 4 + 3] = 0.f;
    }
}

__device__ __forceinline__ float ex2f(float x) {
    float r; asm("ex2.approx.ftz.f32 %0, %1;" : "=f"(r) : "f"(x)); return r;
}
__device__ __forceinline__ float rcpf(float x) {
    float r; asm("rcp.approx.ftz.f32 %0, %1;" : "=f"(r) : "f"(x)); return r;
}

__global__ __launch_bounds__(256) void silhouette_kernel(float* __restrict__ out) {
    __shared__ uint16_t s_idx[8 * FPW];
    __shared__ int s_cnt[8];
    __shared__ int s_deep;

    const int tid = threadIdx.x;
    const int w = tid >> 5;
    const int lane = tid & 31;
    const int b = blockIdx.z;
    const int x0 = blockIdx.x * TILE;
    const int y0 = blockIdx.y * TILE;

    if (tid == 0) s_deep = 0;
    __syncthreads();

    // thresholds in log2-scaled sigmoid units (d_log2 = (dist/sigma)*log2e)
    const float DEAD = -28.853900817779268f;  // -20 * log2(e): sigmoid < 2.1e-9
    const float DEEP = 23.083120654223415f;   //  16 * log2(e): prob > clip surely
    const float STEP = 2.0f / S_;

    // ---------- Phase A: per-warp tile culling over contiguous face segment ----------
    {
        const float cx = (x0 + 8.0f) * STEP - 1.0f;   // tile center (= lin(x0+7.5))
        const float cy = (y0 + 8.0f) * STEP - 1.0f;
        const float hx = 15.0f / S_ + 1e-4f;          // half extent + margin (NDC)
        const float hy = hx;

        const float* cb = g_coeffs + (size_t)b * F_ * 12;
        int lo = w * FPW;
        int hi = min(lo + FPW, F_);
        int cnt = 0, ndeep = 0;
        for (int base = lo; base < hi; base += 32) {
            int f = base + lane;
            bool valid = (f < hi);
            bool active = false, deep = false;
            if (valid) {
                const float4* cp = (const float4*)(cb + (size_t)f * 12);
                float4 e0 = cp[0], e1 = cp[1], e2 = cp[2];
                float dc0 = fmaf(e0.x, cx, fmaf(e0.y, cy, e0.z));
                float dc1 = fmaf(e1.x, cx, fmaf(e1.y, cy, e1.z));
                float dc2 = fmaf(e2.x, cx, fmaf(e2.y, cy, e2.z));
                float ex0 = fmaf(fabsf(e0.x), hx, fabsf(e0.y) * hy);
                float ex1 = fmaf(fabsf(e1.x), hx, fabsf(e1.y) * hy);
                float ex2_ = fmaf(fabsf(e2.x), hx, fabsf(e2.y) * hy);
                bool dead = (dc0 + ex0 < DEAD) || (dc1 + ex1 < DEAD) || (dc2 + ex2_ < DEAD);
                deep = (dc0 - ex0 > DEEP) && (dc1 - ex1 > DEEP) && (dc2 - ex2_ > DEEP);
                active = !dead && !deep;
            }
            unsigned balA = __ballot_sync(0xffffffffu, active);
            if (active) {
                int pos = cnt + __popc(balA & ((1u << lane) - 1u));
                s_idx[lo + pos] = (uint16_t)f;
            }
            cnt += __popc(balA);
            unsigned balD = __ballot_sync(0xffffffffu, deep);
            if (lane == 0) ndeep += __popc(balD);
        }
        if (lane == 0) {
            s_cnt[w] = cnt;
            atomicAdd(&s_deep, ndeep);
        }
    }
    __syncthreads();

    // ---------- Phase B: per-pixel evaluation over active faces ----------
    const int pxi = x0 + (tid & 15);
    const int pyi = y0 + (tid >> 4);
    const float px = (pxi + 0.5f) * STEP - 1.0f;
    const float py = (pyi + 0.5f) * STEP - 1.0f;

    const float CLIPV = 1.0f - 1e-6f;
    const float RMIN = 1.0f - CLIPV;   // exact fp32 clip residue, matches reference

    // deep-face constant factor: RMIN^n (underflows to 0 for n>=8, same as ref's exp(acc))
    float W = 1.0f;
    {
        int nd = s_deep;
        if (nd >= 8) {
            W = 0.0f;
        } else {
            for (int i = 0; i < nd; i++) W *= RMIN;
        }
    }

    const float* cb = g_coeffs + (size_t)b * F_ * 12;
    for (int s = 0; s < 8; s++) {
        int n = s_cnt[s];
        const uint16_t* ip = s_idx + s * FPW;
        for (int j = 0; j < n; j++) {
            int f = ip[j];
            const float4* cp = (const float4*)(cb + (size_t)f * 12);
            float4 e0 = __ldg(cp), e1 = __ldg(cp + 1), e2 = __ldg(cp + 2);
            float d0 = fmaf(e0.x, px, fmaf(e0.y, py, e0.z));
            float d1 = fmaf(e1.x, px, fmaf(e1.y, py, e1.z));
            float d2 = fmaf(e2.x, px, fmaf(e2.y, py, e2.z));
            float dmin = fminf(d0, fminf(d1, d2));
            if (dmin > DEAD) {
                // 1 - prob = Q/(1+Q),  Q = (1+t0)(1+t1)(1+t2) - 1, t = exp(-dist/sigma)
                float t0 = ex2f(-d0);
                float t1 = ex2f(-d1);
                float t2 = ex2f(-d2);
                float sA = t1 + t2;
                float pA = t1 * t2;
                float sp = sA + pA;
                float Q = fmaf(t0, sp, t0 + sp);
                float r = Q * rcpf(1.0f + Q);
                r = fminf(fmaxf(r, RMIN), 1.0f);
                W *= r;
            }
        }
    }

    out[((size_t)b * S_ + pyi) * S_ + pxi] = 1.0f - W;
}

extern "C" void kernel_launch(void* const* d_in, const int* in_sizes, int n_in,
                              void* d_out, int out_size) {
    const float* verts = (const float*)d_in[0];
    const int* faces = (const int*)d_in[1];
    float* out = (float*)d_out;

    int total = B_ * F_;
    precompute_kernel<<<(total + 255) / 256, 256>>>(verts, faces);

    dim3 grid(S_ / TILE, S_ / TILE, B_);
    silhouette_kernel<<<grid, 256>>>(out);
}